// round 6
// baseline (speedup 1.0000x reference)
#include <cuda_runtime.h>
#include <cstdint>

#define LOG2E 1.4426950408889634f

// ---------------- scratch (device globals; no allocations allowed) ----------
__device__ float g_part[8 * 64];            // per (b,c) partial sums
__device__ float g_t[64];                   // relu(MLP) * log2(e)
__device__ float g_Wc[64 * 25 * 12];        // composed weights [i][tap][12]:
                                            //   slots 0..8 = k0..k8, 9 = k8 dup, 10..11 = 0
__device__ float g_bc[9 * 25];              // per-tap bias contribution [k][tap]
__device__ float g_bfield[9 * 128 * 128];   // clipped bias field [k][h][w]

// ---------------- asm helpers ------------------------------------------------
__device__ __forceinline__ unsigned long long ld_s_b64(uint32_t addr) {
    unsigned long long v;
    asm volatile("ld.shared.b64 %0, [%1];" : "=l"(v) : "r"(addr));
    return v;
}
__device__ __forceinline__ void ld_s_v2u64(uint32_t addr,
                                           unsigned long long& a, unsigned long long& b) {
    asm volatile("ld.shared.v2.u64 {%0, %1}, [%2];" : "=l"(a), "=l"(b) : "r"(addr));
}
__device__ __forceinline__ void st_s_dup(uint32_t addr, float v) {
    asm volatile("st.shared.v2.f32 [%0], {%1, %2};" :: "r"(addr), "f"(v), "f"(v));
}
__device__ __forceinline__ void fma2(unsigned long long& acc,
                                     unsigned long long a, unsigned long long b) {
    asm("fma.rn.f32x2 %0, %1, %2, %0;" : "+l"(acc) : "l"(a), "l"(b));
}
__device__ __forceinline__ unsigned long long pack_ab(unsigned long long a,
                                                      unsigned long long b) {
    unsigned long long v;
    asm("mov.b64 %0, {%1, %2};" : "=l"(v) : "r"((uint32_t)a), "r"((uint32_t)b));
    return v;
}
__device__ __forceinline__ int reflect_idx(int i) {
    // numpy 'reflect' (no edge repeat), valid for pad <= 2 on size 128
    if (i < 0) return -i;
    if (i > 127) return 254 - i;
    return i;
}

// ---------------- P1: chansum (blocks 0..511) + compose weights (512..586) --
__global__ void k_prep1(const float* __restrict__ x, const float* __restrict__ w1,
                        const float* __restrict__ b1, const float* __restrict__ w2) {
    int blk = blockIdx.x;
    int tid = threadIdx.x;   // 256
    if (blk < 512) {
        int c = blk & 63, b = blk >> 6;
        const float4* p = (const float4*)(x + (size_t)(b * 64 + c) * 16384);
        float s = 0.f;
        for (int i = tid; i < 4096; i += 256) {
            float4 v = p[i];
            s += v.x + v.y + v.z + v.w;
        }
        __shared__ float sh[256];
        sh[tid] = s;
        __syncthreads();
        for (int o = 128; o > 0; o >>= 1) {
            if (tid < o) sh[tid] += sh[tid + o];
            __syncthreads();
        }
        if (tid == 0) g_part[b * 64 + c] = sh[0];
    } else {
        int idx = (blk - 512) * 256 + tid;       // 0..19199
        if (idx < 19200) {
            int i = idx / 300, rem = idx % 300;
            int tap = rem / 12, slot = rem % 12;
            float s = 0.f;
            if (slot < 10) {
                int kk = (slot >= 8) ? 8 : slot;   // slot 9 duplicates k8
                #pragma unroll 8
                for (int o = 0; o < 64; ++o)
                    s += w2[(kk * 64 + o) * 25 + tap] * w1[o * 64 + i];
            }
            g_Wc[idx] = s;
        }
        if (idx < 225) {
            int k = idx / 25, tap = idx % 25;
            float s = 0.f;
            #pragma unroll 8
            for (int o = 0; o < 64; ++o)
                s += w2[(k * 64 + o) * 25 + tap] * b1[o];
            g_bc[idx] = s;
        }
    }
}

// ---------------- P2: bfield (blocks 0..63) + MLP (block 64) ----------------
__global__ void k_prep2(const float* __restrict__ tc1, const float* __restrict__ tc2) {
    int blk = blockIdx.x;
    int tid = threadIdx.x;   // 256
    if (blk == 64) {
        __shared__ float smean[64];
        __shared__ float sh1[16];
        if (tid < 64) {
            float s = 0.f;
            #pragma unroll
            for (int b = 0; b < 8; ++b) s += g_part[b * 64 + tid];
            smean[tid] = s * (1.f / 131072.f);
        }
        __syncthreads();
        if (tid < 16) {
            float a = 0.f;
            #pragma unroll
            for (int c = 0; c < 64; ++c) a += tc1[tid * 64 + c] * smean[c];
            sh1[tid] = fmaxf(a, 0.f);
        }
        __syncthreads();
        if (tid < 64) {
            float a = 0.f;
            #pragma unroll
            for (int j = 0; j < 16; ++j) a += tc2[tid * 16 + j] * sh1[j];
            g_t[tid] = fmaxf(a, 0.f) * LOG2E;
        }
        return;
    }
    __shared__ float sbc[225];
    if (tid < 225) sbc[tid] = g_bc[tid];
    __syncthreads();
    int pix = blk * 256 + tid;
    int h = pix >> 7, w = pix & 127;
    #pragma unroll
    for (int k = 0; k < 9; ++k) {
        float s = 0.f;
        #pragma unroll
        for (int dy = 0; dy < 5; ++dy) {
            int ih = h + dy - 2;
            if (ih < 0 || ih > 127) continue;
            #pragma unroll
            for (int dx = 0; dx < 5; ++dx) {
                int iw = w + dx - 2;
                if (iw < 0 || iw > 127) continue;
                s += sbc[k * 25 + dy * 5 + dx];
            }
        }
        g_bfield[k * 16384 + pix] = s;
    }
}

// ---------------- main fused kernel ------------------------------------------
// Grid (4,8,8): 32x16 output tile; block (32,4) = 128 threads.
// Thread (tx,ty) owns 4 CONSECUTIVE output rows ty*4+j (j=0..3), column tx.
// Phase 1: 5x5 conv (Cin 64 -> 9 logits) with x rows cached in registers.
// Phase 2: + bias field, per-pixel max-shift.
// Phase 3: per-channel softmax(ak*t) * 3x3 reflect patches -> out.
//
// Dynamic smem layout (bytes):
//   [0, 9600)        sW   : 8 ch x 25 taps x 12 floats (48 B/tap, 16-aligned)
//   [9600, 55680)    sXp  : 8 ch x 20 x 36 dup pairs (phase 1, zero pad)
//                    sXf  : overlay, 8 ch x 20 x 36 floats (phase 3, reflect)
//   [55680, 55936)   sT   : 64 floats
__global__ void __launch_bounds__(128) k_main(const float* __restrict__ x,
                                              float* __restrict__ out) {
    extern __shared__ float sdyn[];
    int tx = threadIdx.x, ty = threadIdx.y;
    int tid = ty * 32 + tx;
    int h0 = blockIdx.y * 16, w0 = blockIdx.x * 32;
    int bz = blockIdx.z;
    const float* xb = x + (size_t)bz * 64 * 16384;

    uint32_t sbase = (uint32_t)__cvta_generic_to_shared(sdyn);
    uint32_t sW = sbase;                 // bytes
    uint32_t sXp = sbase + 9600;         // dup pairs
    float* sXf = sdyn + 2400;            // float overlay of pair region
    float* sT  = sdyn + 13920;

    if (tid < 64) sT[tid] = g_t[tid];

    unsigned long long acc[4][4];    // [j][pair] = k0..k7
    unsigned long long acc8[2];      // [jp] = {k8@j=2jp, k8@j=2jp+1}
    #pragma unroll
    for (int j = 0; j < 4; ++j)
        #pragma unroll
        for (int p = 0; p < 4; ++p) acc[j][p] = 0ull;
    acc8[0] = acc8[1] = 0ull;

    // ---------------- phase 1: conv ----------------
    for (int c0 = 0; c0 < 64; c0 += 8) {
        __syncthreads();
        for (int i = tid; i < 2400; i += 128) sdyn[i] = g_Wc[c0 * 300 + i];
        #pragma unroll 5
        for (int i = tid; i < 5760; i += 128) {
            int c = i / 720, rem = i % 720;
            int y = rem / 36, xx = rem % 36;
            int gh = h0 + y - 2, gw = w0 + xx - 2;
            float v = 0.f;
            if (gh >= 0 && gh < 128 && gw >= 0 && gw < 128)
                v = xb[(size_t)(c0 + c) * 16384 + gh * 128 + gw];
            st_s_dup(sXp + i * 8, v);
        }
        __syncthreads();

        #pragma unroll 1
        for (int c = 0; c < 8; ++c) {
            // register cache: 8 input rows x 5 positions (dup pairs)
            uint32_t xbase = sXp + (c * 720 + (ty * 4) * 36 + tx) * 8;
            unsigned long long xr[8][5];
            #pragma unroll
            for (int r = 0; r < 8; ++r)
                #pragma unroll
                for (int q = 0; q < 5; ++q)
                    xr[r][q] = ld_s_b64(xbase + r * 288 + q * 8);

            uint32_t wb = sW + c * 1200;
            #pragma unroll
            for (int dy = 0; dy < 5; ++dy) {
                #pragma unroll
                for (int dx = 0; dx < 5; ++dx) {
                    uint32_t wp = wb + (dy * 5 + dx) * 48;
                    unsigned long long wv0, wv1, wv2, wv3, wv8;
                    ld_s_v2u64(wp, wv0, wv1);
                    ld_s_v2u64(wp + 16, wv2, wv3);
                    wv8 = ld_s_b64(wp + 32);
                    #pragma unroll
                    for (int jp = 0; jp < 2; ++jp) {
                        unsigned long long xa = xr[2 * jp + dy][dx];
                        unsigned long long xc2 = xr[2 * jp + 1 + dy][dx];
                        fma2(acc[2 * jp][0], wv0, xa);
                        fma2(acc[2 * jp][1], wv1, xa);
                        fma2(acc[2 * jp][2], wv2, xa);
                        fma2(acc[2 * jp][3], wv3, xa);
                        fma2(acc[2 * jp + 1][0], wv0, xc2);
                        fma2(acc[2 * jp + 1][1], wv1, xc2);
                        fma2(acc[2 * jp + 1][2], wv2, xc2);
                        fma2(acc[2 * jp + 1][3], wv3, xc2);
                        fma2(acc8[jp], wv8, pack_ab(xa, xc2));
                    }
                }
            }
        }
    }

    // ---------------- phase 2: bias field + max shift ----------------
    float ak[4][9];
    #pragma unroll
    for (int j = 0; j < 4; ++j) {
        int pix = (h0 + ty * 4 + j) * 128 + w0 + tx;
        float v[9];
        #pragma unroll
        for (int p = 0; p < 4; ++p) {
            v[2 * p]     = __uint_as_float((uint32_t)acc[j][p]);
            v[2 * p + 1] = __uint_as_float((uint32_t)(acc[j][p] >> 32));
        }
        unsigned long long a8 = acc8[j >> 1];
        v[8] = (j & 1) ? __uint_as_float((uint32_t)(a8 >> 32))
                       : __uint_as_float((uint32_t)a8);
        float M = -1e30f;
        #pragma unroll
        for (int k = 0; k < 9; ++k) {
            v[k] += g_bfield[k * 16384 + pix];
            M = fmaxf(M, v[k]);
        }
        #pragma unroll
        for (int k = 0; k < 9; ++k) ak[j][k] = v[k] - M;   // <= 0; t >= 0
    }

    // ---------------- phase 3: softmax gather ----------------
    // Staged tile row y <-> global row h0 + y - 2, col xx <-> w0 + xx - 2.
    // Patch center for local output row lr, col tx is therefore (lr+2, tx+2).
    for (int c0 = 0; c0 < 64; c0 += 8) {
        __syncthreads();
        #pragma unroll 5
        for (int i = tid; i < 5760; i += 128) {
            int c = i / 720, rem = i % 720;
            int y = rem / 36, xx = rem % 36;
            int gh = reflect_idx(h0 + y - 2);
            int gw = reflect_idx(w0 + xx - 2);
            sXf[i] = xb[(size_t)(c0 + c) * 16384 + gh * 128 + gw];
        }
        __syncthreads();

        #pragma unroll 1
        for (int c = 0; c < 8; ++c) {
            float t = sT[c0 + c];
            const float* xc = sXf + c * 720;
            float* ob = out + (size_t)(bz * 64 + c0 + c) * 16384;
            if (t == 0.f) {
                // exp(0)=1 for all 9 taps: exactly uniform attention
                #pragma unroll
                for (int j = 0; j < 4; ++j) {
                    int lr = ty * 4 + j;
                    const float* pr = xc + (lr + 2) * 36 + tx + 2;
                    float s9 = ((pr[-37] + pr[-36]) + (pr[-35] + pr[-1])) +
                               ((pr[0] + pr[1]) + (pr[35] + pr[36])) + pr[37];
                    ob[(h0 + lr) * 128 + w0 + tx] = s9 * (1.f / 9.f);
                }
            } else {
                #pragma unroll
                for (int j = 0; j < 4; ++j) {
                    int lr = ty * 4 + j;
                    const float* pr = xc + (lr + 2) * 36 + tx + 2;
                    float p[9];
                    p[0] = pr[-37]; p[1] = pr[-36]; p[2] = pr[-35];
                    p[3] = pr[-1];  p[4] = pr[0];   p[5] = pr[1];
                    p[6] = pr[35];  p[7] = pr[36];  p[8] = pr[37];
                    float s = 0.f, oo = 0.f;
                    #pragma unroll
                    for (int k = 0; k < 9; ++k) {
                        float e;
                        asm("ex2.approx.ftz.f32 %0, %1;" : "=f"(e) : "f"(ak[j][k] * t));
                        s += e;
                        oo = fmaf(e, p[k], oo);
                    }
                    ob[(h0 + lr) * 128 + w0 + tx] = __fdividef(oo, s);
                }
            }
        }
    }
}

// ---------------- launch ----------------------------------------------------
extern "C" void kernel_launch(void* const* d_in, const int* in_sizes, int n_in,
                              void* d_out, int out_size) {
    const float* x   = (const float*)d_in[0];
    const float* w1  = (const float*)d_in[1];
    const float* b1  = (const float*)d_in[2];
    const float* w2  = (const float*)d_in[3];
    const float* tc1 = (const float*)d_in[4];
    const float* tc2 = (const float*)d_in[5];
    float* out = (float*)d_out;
    (void)in_sizes; (void)n_in; (void)out_size;

    static bool attr_set = false;
    if (!attr_set) {
        cudaFuncSetAttribute(k_main, cudaFuncAttributeMaxDynamicSharedMemorySize, 55936);
        attr_set = true;
    }

    k_prep1<<<587, 256>>>(x, w1, b1, w2);
    k_prep2<<<65, 256>>>(tc1, tc2);
    dim3 gm(4, 8, 8), bm(32, 4);
    k_main<<<gm, bm, 55936>>>(x, out);
}

// round 7
// speedup vs baseline: 1.2337x; 1.2337x over previous
#include <cuda_runtime.h>
#include <cstdint>

#define LOG2E 1.4426950408889634f

// ---------------- scratch (device globals; no allocations allowed) ----------
__device__ float g_part[8 * 64];            // per (b,c) partial sums
__device__ float g_t[64];                   // relu(MLP) * log2(e)
__device__ float g_Wc[64 * 25 * 12];        // composed weights [i][tap][12]:
                                            //   slots 0..8 = k0..k8, 9 = k8 dup, 10..11 = 0
__device__ float g_bc[9 * 25];              // per-tap bias contribution [k][tap]
__device__ float g_bfield[9 * 128 * 128];   // clipped bias field [k][h][w]
__device__ float g_wtA[8 * 9 * 128 * 128];  // conv logits, cin[0:32) + bfield
__device__ float g_wtB[8 * 9 * 128 * 128];  // conv logits, cin[32:64)

// ---------------- asm helpers ------------------------------------------------
__device__ __forceinline__ unsigned long long ld_s_b64(uint32_t addr) {
    unsigned long long v;
    asm volatile("ld.shared.b64 %0, [%1];" : "=l"(v) : "r"(addr));
    return v;
}
__device__ __forceinline__ void ld_s_v2u64(uint32_t addr,
                                           unsigned long long& a, unsigned long long& b) {
    asm volatile("ld.shared.v2.u64 {%0, %1}, [%2];" : "=l"(a), "=l"(b) : "r"(addr));
}
__device__ __forceinline__ void st_s_dup(uint32_t addr, float v) {
    asm volatile("st.shared.v2.f32 [%0], {%1, %2};" :: "r"(addr), "f"(v), "f"(v));
}
__device__ __forceinline__ void fma2(unsigned long long& acc,
                                     unsigned long long a, unsigned long long b) {
    asm("fma.rn.f32x2 %0, %1, %2, %0;" : "+l"(acc) : "l"(a), "l"(b));
}
__device__ __forceinline__ unsigned long long pack_ab(unsigned long long a,
                                                      unsigned long long b) {
    unsigned long long v;
    asm("mov.b64 %0, {%1, %2};" : "=l"(v) : "r"((uint32_t)a), "r"((uint32_t)b));
    return v;
}

// ---------------- P1: chansum (blocks 0..511) + compose weights (512..586) --
__global__ void k_prep1(const float* __restrict__ x, const float* __restrict__ w1,
                        const float* __restrict__ b1, const float* __restrict__ w2) {
    int blk = blockIdx.x;
    int tid = threadIdx.x;   // 256
    if (blk < 512) {
        int c = blk & 63, b = blk >> 6;
        const float4* p = (const float4*)(x + (size_t)(b * 64 + c) * 16384);
        float s0 = 0.f, s1 = 0.f, s2 = 0.f, s3 = 0.f;
        #pragma unroll
        for (int i = 0; i < 16; ++i) {
            float4 v = p[tid + i * 256];
            s0 += v.x; s1 += v.y; s2 += v.z; s3 += v.w;
        }
        float s = (s0 + s1) + (s2 + s3);
        __shared__ float sh[256];
        sh[tid] = s;
        __syncthreads();
        for (int o = 128; o > 0; o >>= 1) {
            if (tid < o) sh[tid] += sh[tid + o];
            __syncthreads();
        }
        if (tid == 0) g_part[b * 64 + c] = sh[0];
    } else {
        int idx = (blk - 512) * 256 + tid;       // 0..19199
        if (idx < 19200) {
            int i = idx / 300, rem = idx % 300;
            int tap = rem / 12, slot = rem % 12;
            float s = 0.f;
            if (slot < 10) {
                int kk = (slot >= 8) ? 8 : slot;   // slot 9 duplicates k8
                #pragma unroll 8
                for (int o = 0; o < 64; ++o)
                    s += w2[(kk * 64 + o) * 25 + tap] * w1[o * 64 + i];
            }
            g_Wc[idx] = s;
        }
        if (idx < 225) {
            int k = idx / 25, tap = idx % 25;
            float s = 0.f;
            #pragma unroll 8
            for (int o = 0; o < 64; ++o)
                s += w2[(k * 64 + o) * 25 + tap] * b1[o];
            g_bc[idx] = s;
        }
    }
}

// ---------------- P2: bfield (blocks 0..63) + MLP (block 64) ----------------
__global__ void k_prep2(const float* __restrict__ tc1, const float* __restrict__ tc2) {
    int blk = blockIdx.x;
    int tid = threadIdx.x;   // 256
    if (blk == 64) {
        __shared__ float smean[64];
        __shared__ float sh1[16];
        if (tid < 64) {
            float s = 0.f;
            #pragma unroll
            for (int b = 0; b < 8; ++b) s += g_part[b * 64 + tid];
            smean[tid] = s * (1.f / 131072.f);
        }
        __syncthreads();
        if (tid < 16) {
            float a = 0.f;
            #pragma unroll
            for (int c = 0; c < 64; ++c) a += tc1[tid * 64 + c] * smean[c];
            sh1[tid] = fmaxf(a, 0.f);
        }
        __syncthreads();
        if (tid < 64) {
            float a = 0.f;
            #pragma unroll
            for (int j = 0; j < 16; ++j) a += tc2[tid * 16 + j] * sh1[j];
            g_t[tid] = fmaxf(a, 0.f) * LOG2E;
        }
        return;
    }
    __shared__ float sbc[225];
    if (tid < 225) sbc[tid] = g_bc[tid];
    __syncthreads();
    int pix = blk * 256 + tid;
    int h = pix >> 7, w = pix & 127;
    #pragma unroll
    for (int k = 0; k < 9; ++k) {
        float s = 0.f;
        #pragma unroll
        for (int dy = 0; dy < 5; ++dy) {
            int ih = h + dy - 2;
            if (ih < 0 || ih > 127) continue;
            #pragma unroll
            for (int dx = 0; dx < 5; ++dx) {
                int iw = w + dx - 2;
                if (iw < 0 || iw > 127) continue;
                s += sbc[k * 25 + dy * 5 + dx];
            }
        }
        g_bfield[k * 16384 + pix] = s;
    }
}

// ---------------- kernel D: 5x5 conv, split over cin halves -----------------
// Grid (4,8,16): 32x16 output tile; z = b*2 + half (half selects cin 32-chunk).
// Block (32,4) = 128 threads; thread owns 4 consecutive rows, column tx.
// Dynamic smem: [0,9600) sW (8ch x 25 taps x 12 fl); [9600,55680) sXp dup pairs.
__global__ void __launch_bounds__(128) k_conv(const float* __restrict__ x) {
    extern __shared__ float sdyn[];
    int tx = threadIdx.x, ty = threadIdx.y;
    int tid = ty * 32 + tx;
    int h0 = blockIdx.y * 16, w0 = blockIdx.x * 32;
    int bz = blockIdx.z >> 1;
    int half = blockIdx.z & 1;
    int cbase = half * 32;
    const float* xb = x + (size_t)bz * 64 * 16384;

    uint32_t sbase = (uint32_t)__cvta_generic_to_shared(sdyn);
    uint32_t sW = sbase;
    uint32_t sXp = sbase + 9600;

    unsigned long long acc[4][4];    // [j][pair] = k0..k7
    unsigned long long acc8[2];      // [jp] = {k8@j=2jp, k8@j=2jp+1}
    #pragma unroll
    for (int j = 0; j < 4; ++j)
        #pragma unroll
        for (int p = 0; p < 4; ++p) acc[j][p] = 0ull;
    acc8[0] = acc8[1] = 0ull;

    for (int c0 = 0; c0 < 32; c0 += 8) {
        __syncthreads();
        for (int i = tid; i < 2400; i += 128) sdyn[i] = g_Wc[(cbase + c0) * 300 + i];
        #pragma unroll 5
        for (int i = tid; i < 5760; i += 128) {
            int c = i / 720, rem = i % 720;
            int y = rem / 36, xx = rem % 36;
            int gh = h0 + y - 2, gw = w0 + xx - 2;
            float v = 0.f;
            if (gh >= 0 && gh < 128 && gw >= 0 && gw < 128)
                v = xb[(size_t)(cbase + c0 + c) * 16384 + gh * 128 + gw];
            st_s_dup(sXp + i * 8, v);
        }
        __syncthreads();

        #pragma unroll 1
        for (int c = 0; c < 8; ++c) {
            // register cache: 8 input rows x 5 positions (dup pairs)
            uint32_t xbase = sXp + (c * 720 + (ty * 4) * 36 + tx) * 8;
            unsigned long long xr[8][5];
            #pragma unroll
            for (int r = 0; r < 8; ++r)
                #pragma unroll
                for (int q = 0; q < 5; ++q)
                    xr[r][q] = ld_s_b64(xbase + r * 288 + q * 8);

            uint32_t wb = sW + c * 1200;
            #pragma unroll
            for (int dy = 0; dy < 5; ++dy) {
                #pragma unroll
                for (int dx = 0; dx < 5; ++dx) {
                    uint32_t wp = wb + (dy * 5 + dx) * 48;
                    unsigned long long wv0, wv1, wv2, wv3, wv8;
                    ld_s_v2u64(wp, wv0, wv1);
                    ld_s_v2u64(wp + 16, wv2, wv3);
                    wv8 = ld_s_b64(wp + 32);
                    #pragma unroll
                    for (int jp = 0; jp < 2; ++jp) {
                        unsigned long long xa = xr[2 * jp + dy][dx];
                        unsigned long long xc2 = xr[2 * jp + 1 + dy][dx];
                        fma2(acc[2 * jp][0], wv0, xa);
                        fma2(acc[2 * jp][1], wv1, xa);
                        fma2(acc[2 * jp][2], wv2, xa);
                        fma2(acc[2 * jp][3], wv3, xa);
                        fma2(acc[2 * jp + 1][0], wv0, xc2);
                        fma2(acc[2 * jp + 1][1], wv1, xc2);
                        fma2(acc[2 * jp + 1][2], wv2, xc2);
                        fma2(acc[2 * jp + 1][3], wv3, xc2);
                        fma2(acc8[jp], wv8, pack_ab(xa, xc2));
                    }
                }
            }
        }
    }

    float* dst = half ? g_wtB : g_wtA;
    int w = w0 + tx;
    #pragma unroll
    for (int j = 0; j < 4; ++j) {
        int h = h0 + ty * 4 + j;
        int pix = h * 128 + w;
        float v[9];
        #pragma unroll
        for (int p = 0; p < 4; ++p) {
            v[2 * p]     = __uint_as_float((uint32_t)acc[j][p]);
            v[2 * p + 1] = __uint_as_float((uint32_t)(acc[j][p] >> 32));
        }
        unsigned long long a8 = acc8[j >> 1];
        v[8] = (j & 1) ? __uint_as_float((uint32_t)(a8 >> 32))
                       : __uint_as_float((uint32_t)a8);
        #pragma unroll
        for (int k = 0; k < 9; ++k) {
            float o = v[k];
            if (half == 0) o += g_bfield[k * 16384 + pix];   // bias only once
            dst[((size_t)bz * 9 + k) * 16384 + pix] = o;
        }
    }
}

// ---------------- kernel E: softmax((A+B)_k * t_c) * 3x3 reflect patches ----
// Grid (128, 8, 2): block = (row h, batch b, output-channel half). 128 threads.
__global__ void __launch_bounds__(128) k_out(const float* __restrict__ x,
                                             float* __restrict__ out) {
    __shared__ float st[64];
    int w = threadIdx.x;       // 0..127
    int h = blockIdx.x;        // 0..127
    int b = blockIdx.y;        // 0..7
    int chalf = blockIdx.z;    // 0..1
    int pix = h * 128 + w;
    if (w < 64) st[w] = g_t[w];
    __syncthreads();

    float ak[9];
    float M = -1e30f;
    #pragma unroll
    for (int k = 0; k < 9; ++k) {
        size_t idx = ((size_t)b * 9 + k) * 16384 + pix;
        ak[k] = g_wtA[idx] + g_wtB[idx];
        M = fmaxf(M, ak[k]);
    }
    #pragma unroll
    for (int k = 0; k < 9; ++k) ak[k] -= M;   // <= 0; t >= 0 so max preserved

    // reflect padding (PAD = 1): -1 -> 1, 128 -> 126
    int hm = (h == 0) ? 1 : h - 1;
    int hp = (h == 127) ? 126 : h + 1;
    int wm = (w == 0) ? 1 : w - 1;
    int wp = (w == 127) ? 126 : w + 1;
    int r0 = hm * 128, r1 = h * 128, r2 = hp * 128;

    const float* xb = x + (size_t)b * 64 * 16384;
    int cbeg = chalf * 32;
    #pragma unroll 1
    for (int c = cbeg; c < cbeg + 32; ++c) {
        const float* xc = xb + (size_t)c * 16384;
        float t = st[c];
        float p[9];
        p[0] = xc[r0 + wm]; p[1] = xc[r0 + w]; p[2] = xc[r0 + wp];
        p[3] = xc[r1 + wm]; p[4] = xc[r1 + w]; p[5] = xc[r1 + wp];
        p[6] = xc[r2 + wm]; p[7] = xc[r2 + w]; p[8] = xc[r2 + wp];
        float o;
        if (t == 0.f) {
            // exp(0)=1 for all 9 taps: exactly uniform attention
            float s9 = ((p[0] + p[1]) + (p[2] + p[3])) + ((p[4] + p[5]) + (p[6] + p[7])) + p[8];
            o = s9 * (1.f / 9.f);
        } else {
            float s = 0.f, oo = 0.f;
            #pragma unroll
            for (int k = 0; k < 9; ++k) {
                float e;
                asm("ex2.approx.ftz.f32 %0, %1;" : "=f"(e) : "f"(ak[k] * t));
                s += e;
                oo = fmaf(e, p[k], oo);
            }
            o = __fdividef(oo, s);
        }
        out[(size_t)(b * 64 + c) * 16384 + pix] = o;
    }
}

// ---------------- launch ----------------------------------------------------
extern "C" void kernel_launch(void* const* d_in, const int* in_sizes, int n_in,
                              void* d_out, int out_size) {
    const float* x   = (const float*)d_in[0];
    const float* w1  = (const float*)d_in[1];
    const float* b1  = (const float*)d_in[2];
    const float* w2  = (const float*)d_in[3];
    const float* tc1 = (const float*)d_in[4];
    const float* tc2 = (const float*)d_in[5];
    float* out = (float*)d_out;
    (void)in_sizes; (void)n_in; (void)out_size;

    static bool attr_set = false;
    if (!attr_set) {
        cudaFuncSetAttribute(k_conv, cudaFuncAttributeMaxDynamicSharedMemorySize, 55680);
        attr_set = true;
    }

    k_prep1<<<587, 256>>>(x, w1, b1, w2);
    k_prep2<<<65, 256>>>(tc1, tc2);
    dim3 gc(4, 8, 16), bc(32, 4);
    k_conv<<<gc, bc, 55680>>>(x);
    dim3 ge(128, 8, 2);
    k_out<<<ge, 128>>>(x, out);
}